// round 1
// baseline (speedup 1.0000x reference)
#include <cuda_runtime.h>
#include <math.h>

#define BATCH   16
#define T       640
#define EMBD    256
#define HEADS   8
#define DHDIM   32
#define BHDIM   128      // BATCH*HEADS
#define NHASH   8
#define NCHUNK  80
#define NROWS   10240    // BATCH*T

// ---------------- scratch (device globals; no allocation allowed) ----------------
__device__ float g_tokens[NROWS*EMBD];                       // 10.5 MB
__device__ float g_qk[BHDIM*T*DHDIM];                        // 10.5 MB
__device__ float g_v [BHDIM*T*DHDIM];                        // 10.5 MB
__device__ int   g_bucket[BHDIM*NHASH*T];                    // 2.6 MB
__device__ int   g_sorted[BHDIM*NHASH*T];                    // 2.6 MB
__device__ float g_ohash[(size_t)BHDIM*NHASH*T*DHDIM];       // 84 MB
__device__ float g_logit[BHDIM*NHASH*T];                     // 2.6 MB
__device__ float g_omerged[NROWS*EMBD];                      // 10.5 MB

// ---------------- stage 1: maxpool + Haar DWT -> tokens ----------------
__global__ void frontend_kernel(const float* __restrict__ x){
  int idx = blockIdx.x*blockDim.x + threadIdx.x;
  if (idx >= BATCH*640*256) return;
  int p = idx & 255;
  int n = (idx >> 8) % 640;
  int b = idx / (640*256);
  int i = p >> 4, j = p & 15;
  float val;
  if (n < 128){
    const float* xp = x + (size_t)(b*128+n)*1024;
    float m = -INFINITY;
    int r0 = 2*i-1, c0 = 2*j-1;
    #pragma unroll
    for (int dr=0;dr<3;dr++){
      int r = r0+dr; if (r<0 || r>31) continue;
      #pragma unroll
      for (int dc=0;dc<3;dc++){
        int cc = c0+dc; if (cc<0 || cc>31) continue;
        m = fmaxf(m, xp[r*32+cc]);
      }
    }
    val = m;
  } else {
    int g  = (n-128)>>7;
    int ch = (n-128)&127;
    const float* xp = x + (size_t)(b*128+ch)*1024;
    float a  = xp[(2*i)*32 + 2*j];
    float bb = xp[(2*i)*32 + 2*j+1];
    float c  = xp[(2*i+1)*32 + 2*j];
    float d  = xp[(2*i+1)*32 + 2*j+1];
    if      (g==0) val = (a+bb+c+d)*0.5f;
    else if (g==1) val = (a-bb+c-d)*0.5f;
    else if (g==2) val = (a+bb-c-d)*0.5f;
    else           val = (a-bb-c+d)*0.5f;
  }
  g_tokens[idx] = val;
}

// ---------------- stage 2: fused qk/v GEMM, head-split epilogue ----------------
__global__ __launch_bounds__(256) void gemm_qkv_kernel(const float* __restrict__ Wqk,
                                                       const float* __restrict__ Wv){
  __shared__ float As [32][64];
  __shared__ float B1s[32][64];
  __shared__ float B2s[32][64];
  int tid = threadIdx.x;
  int m0 = blockIdx.y*64, n0 = blockIdx.x*64;
  int ty = tid>>4, tx = tid&15;
  float acc1[4][4], acc2[4][4];
  #pragma unroll
  for (int i=0;i<4;i++)
    #pragma unroll
    for (int j=0;j<4;j++){ acc1[i][j]=0.f; acc2[i][j]=0.f; }

  for (int k0=0;k0<256;k0+=32){
    int am = tid>>2, akq = tid&3;
    const float* asrc = g_tokens + (size_t)(m0+am)*256 + k0 + akq*8;
    float4 a0 = *(const float4*)asrc;
    float4 a1 = *(const float4*)(asrc+4);
    As[akq*8+0][am]=a0.x; As[akq*8+1][am]=a0.y; As[akq*8+2][am]=a0.z; As[akq*8+3][am]=a0.w;
    As[akq*8+4][am]=a1.x; As[akq*8+5][am]=a1.y; As[akq*8+6][am]=a1.z; As[akq*8+7][am]=a1.w;

    int bk = tid>>3, bnq = tid&7;
    const float* b1src = Wqk + (size_t)(k0+bk)*256 + n0 + bnq*8;
    const float* b2src = Wv  + (size_t)(k0+bk)*256 + n0 + bnq*8;
    *(float4*)&B1s[bk][bnq*8]   = *(const float4*)b1src;
    *(float4*)&B1s[bk][bnq*8+4] = *(const float4*)(b1src+4);
    *(float4*)&B2s[bk][bnq*8]   = *(const float4*)b2src;
    *(float4*)&B2s[bk][bnq*8+4] = *(const float4*)(b2src+4);
    __syncthreads();

    #pragma unroll
    for (int k=0;k<32;k++){
      float4 av = *(float4*)&As [k][ty*4];
      float4 b1 = *(float4*)&B1s[k][tx*4];
      float4 b2 = *(float4*)&B2s[k][tx*4];
      float aa[4]  = {av.x,av.y,av.z,av.w};
      float bb1[4] = {b1.x,b1.y,b1.z,b1.w};
      float bb2[4] = {b2.x,b2.y,b2.z,b2.w};
      #pragma unroll
      for (int i2=0;i2<4;i2++)
        #pragma unroll
        for (int j2=0;j2<4;j2++){
          acc1[i2][j2] += aa[i2]*bb1[j2];
          acc2[i2][j2] += aa[i2]*bb2[j2];
        }
    }
    __syncthreads();
  }
  #pragma unroll
  for (int i2=0;i2<4;i2++){
    int row = m0 + ty*4 + i2;
    int b = row/640, tok = row%640;
    #pragma unroll
    for (int j2=0;j2<4;j2++){
      int col = n0 + tx*4 + j2;
      int head = col>>5, dh = col&31;
      size_t o = ((size_t)(b*8+head)*640 + tok)*32 + dh;
      g_qk[o] = acc1[i2][j2];
      g_v [o] = acc2[i2][j2];
    }
  }
}

// ---------------- stage 3a: LSH bucket ids ----------------
__global__ void bucket_kernel(const float* __restrict__ rot){
  __shared__ float s_rot[32*NHASH*5];  // 1280
  for (int i=threadIdx.x;i<1280;i+=blockDim.x) s_rot[i]=rot[i];
  __syncthreads();
  int idx = blockIdx.x*blockDim.x + threadIdx.x;
  if (idx >= BHDIM*NHASH*T) return;
  int pos = idx % 640;
  int h   = (idx/640) & 7;
  int bh  = idx / (NHASH*T);
  const float* q = g_qk + ((size_t)bh*640 + pos)*32;
  float r[5] = {0.f,0.f,0.f,0.f,0.f};
  #pragma unroll 8
  for (int f=0;f<32;f++){
    float qf = q[f];
    const float* rp = s_rot + f*40 + h*5;
    #pragma unroll
    for (int i=0;i<5;i++) r[i] += qf*rp[i];
  }
  float best = r[0]; int bi = 0;
  #pragma unroll
  for (int i=1;i<5;i++) if (r[i] > best){ best=r[i]; bi=i; }
  #pragma unroll
  for (int i=0;i<5;i++){ float v = -r[i]; if (v > best){ best=v; bi=5+i; } }
  g_bucket[idx] = bi;
}

// ---------------- stage 3b: stable counting sort per (bh, hash) ----------------
// argsort(640*bucket + pos) with hash-disjoint bucket ranges == per-hash
// stable counting sort into 10 bins. One warp per bin.
__global__ __launch_bounds__(320) void sort_kernel(){
  __shared__ int cnt[10], off[10];
  int bhh = blockIdx.x;                 // bh*8+h
  const int* bk = g_bucket + bhh*640;
  int w = threadIdx.x>>5, lane = threadIdx.x&31;
  int count = 0;
  for (int base=0;base<640;base+=32){
    int bb = bk[base+lane];
    unsigned mask = __ballot_sync(0xffffffffu, bb==w);
    count += __popc(mask);
  }
  if (lane==0) cnt[w] = count;
  __syncthreads();
  if (threadIdx.x==0){
    int run=0;
    for (int b=0;b<10;b++){ off[b]=run; run+=cnt[b]; }
  }
  __syncthreads();
  int base_off = off[w]; int run = 0;
  int* out = g_sorted + bhh*640;
  for (int base=0;base<640;base+=32){
    int bb = bk[base+lane];
    unsigned mask = __ballot_sync(0xffffffffu, bb==w);
    if (bb==w){
      int slot = base_off + run + __popc(mask & ((1u<<lane)-1u));
      out[slot] = base+lane;
    }
    run += __popc(mask);
  }
}

// ---------------- stage 4: chunked attention (block per bh x chunk) ----------------
// smem carve: s_q[64*32] | s_k[128*33] | s_v[128*32] | s_dots[64*129] | s_qt[64] | s_kt[128]
#define SMEM_ATTN ((64*32 + 128*33 + 128*32 + 64*129)*4 + (64+128)*4)

__global__ __launch_bounds__(128) void attn_kernel(){
  extern __shared__ char smem_raw[];
  float* s_q    = (float*)smem_raw;         // [64][32]
  float* s_k    = s_q + 64*32;              // [128][33] padded
  float* s_v    = s_k + 128*33;             // [128][32]
  float* s_dots = s_v + 128*32;             // [64][129] padded
  int*   s_qt   = (int*)(s_dots + 64*129);  // [64]
  int*   s_kt   = s_qt + 64;                // [128]

  int tid = threadIdx.x;
  int blk = blockIdx.x;
  int bh = blk / NCHUNK, c = blk % NCHUNK;
  int h  = c / 10;
  int pc = (c + NCHUNK - 1) % NCHUNK;       // look_one_back wraps across whole 80-chunk ring
  int ph = pc / 10;
  const int* sortedbh = g_sorted + bh*NHASH*T;

  if (tid < 64)
    s_qt[tid] = sortedbh[h*640 + (c%10)*64 + tid];
  {
    int j = tid;
    int t = (j < 64) ? sortedbh[h*640 + (c%10)*64 + j]
                     : sortedbh[ph*640 + (pc%10)*64 + (j-64)];
    s_kt[j] = t;
  }
  __syncthreads();

  // load queries (unnormalized)
  {
    int row = tid >> 1, half = tid & 1;
    const float* src = g_qk + ((size_t)bh*640 + s_qt[row])*32 + half*16;
    float* dst = s_q + row*32 + half*16;
    #pragma unroll
    for (int t=0;t<16;t+=4) *(float4*)(dst+t) = *(const float4*)(src+t);
  }
  // load keys + row-normalize (norm = max(||row||, 1e-6))
  {
    const float* src = g_qk + ((size_t)bh*640 + s_kt[tid])*32;
    float buf[32]; float ss = 0.f;
    #pragma unroll
    for (int t=0;t<32;t++){ buf[t]=src[t]; ss += buf[t]*buf[t]; }
    float inv = 1.f / fmaxf(sqrtf(ss), 1e-6f);
    #pragma unroll
    for (int t=0;t<32;t++) s_k[tid*33+t] = buf[t]*inv;
  }
  // load values
  {
    const float* src = g_v + ((size_t)bh*640 + s_kt[tid])*32;
    #pragma unroll
    for (int t=0;t<32;t+=4) *(float4*)(s_v + tid*32 + t) = *(const float4*)(src+t);
  }
  __syncthreads();

  // dots: thread owns (row i, half of j range); q row in registers
  {
    int i = tid >> 1, half = tid & 1;
    float qr[32];
    #pragma unroll
    for (int k=0;k<32;k++) qr[k] = s_q[i*32+k];
    int qtok = s_qt[i];
    for (int jj=0;jj<64;jj++){
      int j = half*64 + jj;
      float acc = 0.f;
      #pragma unroll
      for (int k=0;k<32;k++) acc += qr[k]*s_k[j*33+k];
      acc *= 0.17677669529663687f;           // 32^-0.5
      if (s_kt[j] == qtok) acc = -50000.f;
      s_dots[i*129 + j] = acc;
    }
  }
  __syncthreads();

  // row softmax + lse; warp handles 16 rows
  {
    int wid = tid>>5, lane = tid&31;
    for (int i = wid*16; i < wid*16+16; i++){
      float v0 = s_dots[i*129+lane];
      float v1 = s_dots[i*129+lane+32];
      float v2 = s_dots[i*129+lane+64];
      float v3 = s_dots[i*129+lane+96];
      float m = fmaxf(fmaxf(v0,v1), fmaxf(v2,v3));
      #pragma unroll
      for (int o=16;o>0;o>>=1) m = fmaxf(m, __shfl_xor_sync(0xffffffffu, m, o));
      float s = expf(v0-m)+expf(v1-m)+expf(v2-m)+expf(v3-m);
      #pragma unroll
      for (int o=16;o>0;o>>=1) s += __shfl_xor_sync(0xffffffffu, s, o);
      float lse = m + logf(s);
      s_dots[i*129+lane]    = expf(v0-lse);
      s_dots[i*129+lane+32] = expf(v1-lse);
      s_dots[i*129+lane+64] = expf(v2-lse);
      s_dots[i*129+lane+96] = expf(v3-lse);
      if (lane==0) g_logit[(bh*NHASH+h)*T + s_qt[i]] = lse;
    }
  }
  __syncthreads();

  // PV: thread owns (row i, 16 of 32 dims); scatter by original position (undo fused)
  {
    int i = tid >> 1, half = tid & 1;
    float acc[16];
    #pragma unroll
    for (int d=0;d<16;d++) acc[d]=0.f;
    for (int j=0;j<128;j++){
      float p = s_dots[i*129+j];
      #pragma unroll
      for (int d=0;d<16;d++) acc[d] += p * s_v[j*32 + half*16 + d];
    }
    float* dst = g_ohash + ((size_t)(bh*NHASH+h)*T + s_qt[i])*32 + half*16;
    #pragma unroll
    for (int d=0;d<16;d++) dst[d] = acc[d];
  }
}

// ---------------- stage 5: combine hashes, merge heads ----------------
__global__ void combine_kernel(){
  int idx = blockIdx.x*blockDim.x + threadIdx.x;
  if (idx >= BHDIM*T*DHDIM) return;
  int d   = idx & 31;
  int pos = (idx >> 5) % 640;
  int bh  = idx / (640*32);
  float l[NHASH];
  #pragma unroll
  for (int h=0;h<NHASH;h++) l[h] = g_logit[(bh*NHASH+h)*T + pos];
  float m = l[0];
  #pragma unroll
  for (int h=1;h<NHASH;h++) m = fmaxf(m, l[h]);
  float s = 0.f;
  float e[NHASH];
  #pragma unroll
  for (int h=0;h<NHASH;h++){ e[h] = expf(l[h]-m); s += e[h]; }
  float inv = 1.f/s;
  float acc = 0.f;
  #pragma unroll
  for (int h=0;h<NHASH;h++)
    acc += (e[h]*inv) * g_ohash[((size_t)(bh*NHASH+h)*T + pos)*32 + d];
  int b = bh>>3, head = bh&7;
  g_omerged[((size_t)b*640 + pos)*256 + head*32 + d] = acc;
}

// ---------------- stage 6: output GEMM + bias ----------------
__global__ __launch_bounds__(256) void gemm_out_kernel(const float* __restrict__ W,
                                                       const float* __restrict__ bias,
                                                       float* __restrict__ out){
  __shared__ float As[32][64];
  __shared__ float Bs[32][64];
  int tid = threadIdx.x;
  int m0 = blockIdx.y*64, n0 = blockIdx.x*64;
  int ty = tid>>4, tx = tid&15;
  float acc[4][4];
  #pragma unroll
  for (int i=0;i<4;i++)
    #pragma unroll
    for (int j=0;j<4;j++) acc[i][j]=0.f;

  for (int k0=0;k0<256;k0+=32){
    int am = tid>>2, akq = tid&3;
    const float* asrc = g_omerged + (size_t)(m0+am)*256 + k0 + akq*8;
    float4 a0 = *(const float4*)asrc;
    float4 a1 = *(const float4*)(asrc+4);
    As[akq*8+0][am]=a0.x; As[akq*8+1][am]=a0.y; As[akq*8+2][am]=a0.z; As[akq*8+3][am]=a0.w;
    As[akq*8+4][am]=a1.x; As[akq*8+5][am]=a1.y; As[akq*8+6][am]=a1.z; As[akq*8+7][am]=a1.w;

    int bk = tid>>3, bnq = tid&7;
    const float* bsrc = W + (size_t)(k0+bk)*256 + n0 + bnq*8;
    *(float4*)&Bs[bk][bnq*8]   = *(const float4*)bsrc;
    *(float4*)&Bs[bk][bnq*8+4] = *(const float4*)(bsrc+4);
    __syncthreads();

    #pragma unroll
    for (int k=0;k<32;k++){
      float4 av = *(float4*)&As[k][ty*4];
      float4 bv = *(float4*)&Bs[k][tx*4];
      float aa[4] = {av.x,av.y,av.z,av.w};
      float bb[4] = {bv.x,bv.y,bv.z,bv.w};
      #pragma unroll
      for (int i2=0;i2<4;i2++)
        #pragma unroll
        for (int j2=0;j2<4;j2++) acc[i2][j2] += aa[i2]*bb[j2];
    }
    __syncthreads();
  }
  #pragma unroll
  for (int i2=0;i2<4;i2++){
    int row = m0 + ty*4 + i2;
    #pragma unroll
    for (int j2=0;j2<4;j2++){
      int col = n0 + tx*4 + j2;
      out[(size_t)row*256 + col] = acc[i2][j2] + bias[col];
    }
  }
}

// ---------------- launch ----------------
extern "C" void kernel_launch(void* const* d_in, const int* in_sizes, int n_in,
                              void* d_out, int out_size){
  const float* x     = (const float*)d_in[0];
  const float* w_qk  = (const float*)d_in[1];
  const float* w_v   = (const float*)d_in[2];
  const float* w_out = (const float*)d_in[3];
  const float* b_out = (const float*)d_in[4];
  const float* rot   = (const float*)d_in[5];
  float* out = (float*)d_out;

  frontend_kernel<<<(BATCH*640*256+255)/256, 256>>>(x);
  gemm_qkv_kernel<<<dim3(4,160), 256>>>(w_qk, w_v);
  bucket_kernel<<<(BHDIM*NHASH*T+255)/256, 256>>>(rot);
  sort_kernel<<<BHDIM*NHASH, 320>>>();
  cudaFuncSetAttribute(attn_kernel, cudaFuncAttributeMaxDynamicSharedMemorySize, SMEM_ATTN);
  attn_kernel<<<BHDIM*NCHUNK, 128, SMEM_ATTN>>>();
  combine_kernel<<<(BHDIM*T*DHDIM+255)/256, 256>>>();
  gemm_out_kernel<<<dim3(4,160), 256>>>(w_out, b_out, out);
}

// round 2
// speedup vs baseline: 2.0118x; 2.0118x over previous
#include <cuda_runtime.h>
#include <math.h>

#define BATCH   16
#define T       640
#define EMBD    256
#define HEADS   8
#define DHDIM   32
#define BHDIM   128      // BATCH*HEADS
#define NHASH   8
#define NCHUNK  80
#define NROWS   10240    // BATCH*T

// ---------------- scratch (device globals; no allocation allowed) ----------------
__device__ float g_tokens[NROWS*EMBD];
__device__ float g_qk[BHDIM*T*DHDIM];
__device__ float g_v [BHDIM*T*DHDIM];
__device__ int   g_bucket[BHDIM*NHASH*T];
__device__ int   g_sorted[BHDIM*NHASH*T];
__device__ float g_ohash[(size_t)BHDIM*NHASH*T*DHDIM];
__device__ float g_logit[BHDIM*NHASH*T];
__device__ float g_omerged[NROWS*EMBD];

// ---------------- stage 1: maxpool + Haar DWT -> tokens ----------------
__global__ void frontend_kernel(const float* __restrict__ x){
  int idx = blockIdx.x*blockDim.x + threadIdx.x;
  if (idx >= BATCH*640*256) return;
  int p = idx & 255;
  int n = (idx >> 8) % 640;
  int b = idx / (640*256);
  int i = p >> 4, j = p & 15;
  float val;
  if (n < 128){
    const float* xp = x + (size_t)(b*128+n)*1024;
    float m = -INFINITY;
    int r0 = 2*i-1, c0 = 2*j-1;
    #pragma unroll
    for (int dr=0;dr<3;dr++){
      int r = r0+dr; if (r<0 || r>31) continue;
      #pragma unroll
      for (int dc=0;dc<3;dc++){
        int cc = c0+dc; if (cc<0 || cc>31) continue;
        m = fmaxf(m, xp[r*32+cc]);
      }
    }
    val = m;
  } else {
    int g  = (n-128)>>7;
    int ch = (n-128)&127;
    const float* xp = x + (size_t)(b*128+ch)*1024;
    float a  = xp[(2*i)*32 + 2*j];
    float bb = xp[(2*i)*32 + 2*j+1];
    float c  = xp[(2*i+1)*32 + 2*j];
    float d  = xp[(2*i+1)*32 + 2*j+1];
    if      (g==0) val = (a+bb+c+d)*0.5f;
    else if (g==1) val = (a-bb+c-d)*0.5f;
    else if (g==2) val = (a+bb-c-d)*0.5f;
    else           val = (a-bb-c+d)*0.5f;
  }
  g_tokens[idx] = val;
}

// ---------------- stage 2: fused qk/v GEMM, head-split epilogue ----------------
__global__ __launch_bounds__(256) void gemm_qkv_kernel(const float* __restrict__ Wqk,
                                                       const float* __restrict__ Wv){
  __shared__ float As [32][64];
  __shared__ float B1s[32][64];
  __shared__ float B2s[32][64];
  int tid = threadIdx.x;
  int m0 = blockIdx.y*64, n0 = blockIdx.x*64;
  int ty = tid>>4, tx = tid&15;
  float acc1[4][4], acc2[4][4];
  #pragma unroll
  for (int i=0;i<4;i++)
    #pragma unroll
    for (int j=0;j<4;j++){ acc1[i][j]=0.f; acc2[i][j]=0.f; }

  for (int k0=0;k0<256;k0+=32){
    int am = tid>>2, akq = tid&3;
    const float* asrc = g_tokens + (size_t)(m0+am)*256 + k0 + akq*8;
    float4 a0 = *(const float4*)asrc;
    float4 a1 = *(const float4*)(asrc+4);
    As[akq*8+0][am]=a0.x; As[akq*8+1][am]=a0.y; As[akq*8+2][am]=a0.z; As[akq*8+3][am]=a0.w;
    As[akq*8+4][am]=a1.x; As[akq*8+5][am]=a1.y; As[akq*8+6][am]=a1.z; As[akq*8+7][am]=a1.w;

    int bk = tid>>3, bnq = tid&7;
    const float* b1src = Wqk + (size_t)(k0+bk)*256 + n0 + bnq*8;
    const float* b2src = Wv  + (size_t)(k0+bk)*256 + n0 + bnq*8;
    *(float4*)&B1s[bk][bnq*8]   = *(const float4*)b1src;
    *(float4*)&B1s[bk][bnq*8+4] = *(const float4*)(b1src+4);
    *(float4*)&B2s[bk][bnq*8]   = *(const float4*)b2src;
    *(float4*)&B2s[bk][bnq*8+4] = *(const float4*)(b2src+4);
    __syncthreads();

    #pragma unroll
    for (int k=0;k<32;k++){
      float4 av = *(float4*)&As [k][ty*4];
      float4 b1 = *(float4*)&B1s[k][tx*4];
      float4 b2 = *(float4*)&B2s[k][tx*4];
      float aa[4]  = {av.x,av.y,av.z,av.w};
      float bb1[4] = {b1.x,b1.y,b1.z,b1.w};
      float bb2[4] = {b2.x,b2.y,b2.z,b2.w};
      #pragma unroll
      for (int i2=0;i2<4;i2++)
        #pragma unroll
        for (int j2=0;j2<4;j2++){
          acc1[i2][j2] += aa[i2]*bb1[j2];
          acc2[i2][j2] += aa[i2]*bb2[j2];
        }
    }
    __syncthreads();
  }
  #pragma unroll
  for (int i2=0;i2<4;i2++){
    int row = m0 + ty*4 + i2;
    int b = row/640, tok = row%640;
    #pragma unroll
    for (int j2=0;j2<4;j2++){
      int col = n0 + tx*4 + j2;
      int head = col>>5, dh = col&31;
      size_t o = ((size_t)(b*8+head)*640 + tok)*32 + dh;
      g_qk[o] = acc1[i2][j2];
      g_v [o] = acc2[i2][j2];
    }
  }
}

// ---------------- stage 3a: LSH bucket ids ----------------
__global__ void bucket_kernel(const float* __restrict__ rot){
  __shared__ float s_rot[32*NHASH*5];
  for (int i=threadIdx.x;i<1280;i+=blockDim.x) s_rot[i]=rot[i];
  __syncthreads();
  int idx = blockIdx.x*blockDim.x + threadIdx.x;
  if (idx >= BHDIM*NHASH*T) return;
  int pos = idx % 640;
  int h   = (idx/640) & 7;
  int bh  = idx / (NHASH*T);
  const float* q = g_qk + ((size_t)bh*640 + pos)*32;
  float r[5] = {0.f,0.f,0.f,0.f,0.f};
  #pragma unroll 8
  for (int f=0;f<32;f++){
    float qf = q[f];
    const float* rp = s_rot + f*40 + h*5;
    #pragma unroll
    for (int i=0;i<5;i++) r[i] += qf*rp[i];
  }
  float best = r[0]; int bi = 0;
  #pragma unroll
  for (int i=1;i<5;i++) if (r[i] > best){ best=r[i]; bi=i; }
  #pragma unroll
  for (int i=0;i<5;i++){ float v = -r[i]; if (v > best){ best=v; bi=5+i; } }
  g_bucket[idx] = bi;
}

// ---------------- stage 3b: stable counting sort per (bh, hash) ----------------
__global__ __launch_bounds__(320) void sort_kernel(){
  __shared__ int cnt[10], off[10];
  int bhh = blockIdx.x;
  const int* bk = g_bucket + bhh*640;
  int w = threadIdx.x>>5, lane = threadIdx.x&31;
  int count = 0;
  for (int base=0;base<640;base+=32){
    int bb = bk[base+lane];
    unsigned mask = __ballot_sync(0xffffffffu, bb==w);
    count += __popc(mask);
  }
  if (lane==0) cnt[w] = count;
  __syncthreads();
  if (threadIdx.x==0){
    int run=0;
    for (int b=0;b<10;b++){ off[b]=run; run+=cnt[b]; }
  }
  __syncthreads();
  int base_off = off[w]; int run = 0;
  int* out = g_sorted + bhh*640;
  for (int base=0;base<640;base+=32){
    int bb = bk[base+lane];
    unsigned mask = __ballot_sync(0xffffffffu, bb==w);
    if (bb==w){
      int slot = base_off + run + __popc(mask & ((1u<<lane)-1u));
      out[slot] = base+lane;
    }
    run += __popc(mask);
  }
}

// ---------------- stage 4: chunked attention, register-tiled ----------------
// smem layout:
//   s_p  : [64][132] floats (33792 B)   -- aliased during dots by:
//       s_qT : [32][68]  (8704 B)
//       s_kT : [32][132] (16896 B)  (8704+16896 = 25600 <= 33792, fits)
//   s_v  : [128][32] floats (16384 B)
//   s_qt : [64] int, s_kt : [128] int
#define QT_PAD 68
#define KT_PAD 132
#define P_PAD  132
#define SMEM_ATTN ((64*P_PAD + 128*32)*4 + (64+128)*4)

__global__ __launch_bounds__(256) void attn_kernel(){
  extern __shared__ char smem_raw[];
  float* s_p  = (float*)smem_raw;            // [64][132]
  float* s_qT = s_p;                         // [32][68]   (aliased)
  float* s_kT = s_qT + 32*QT_PAD;            // [32][132]  (aliased)
  float* s_v  = s_p + 64*P_PAD;              // [128][32]
  int*   s_qt = (int*)(s_v + 128*32);        // [64]
  int*   s_kt = s_qt + 64;                   // [128]

  int tid = threadIdx.x;
  int blk = blockIdx.x;
  int bh = blk / NCHUNK, c = blk % NCHUNK;
  int h  = c / 10;
  int pc = (c + NCHUNK - 1) % NCHUNK;
  int ph = pc / 10;
  const int* sortedbh = g_sorted + bh*NHASH*T;

  if (tid < 64)
    s_qt[tid] = sortedbh[h*640 + (c%10)*64 + tid];
  else if (tid < 192){
    int j = tid - 64;
    s_kt[j] = (j < 64) ? sortedbh[h*640 + (c%10)*64 + j]
                       : sortedbh[ph*640 + (pc%10)*64 + (j-64)];
  }
  __syncthreads();

  // Load Q feature-major: thread t -> token i=t/4, feature block f=(t%4)*8
  {
    int i = tid >> 2, f = (tid & 3) * 8;
    const float* src = g_qk + ((size_t)bh*640 + s_qt[i])*32 + f;
    float4 a = *(const float4*)src;
    float4 b = *(const float4*)(src+4);
    s_qT[(f+0)*QT_PAD+i]=a.x; s_qT[(f+1)*QT_PAD+i]=a.y;
    s_qT[(f+2)*QT_PAD+i]=a.z; s_qT[(f+3)*QT_PAD+i]=a.w;
    s_qT[(f+4)*QT_PAD+i]=b.x; s_qT[(f+5)*QT_PAD+i]=b.y;
    s_qT[(f+6)*QT_PAD+i]=b.z; s_qT[(f+7)*QT_PAD+i]=b.w;
  }
  // Load K feature-major + normalize; thread t -> token j=t/2, half fh=(t%2)*16
  {
    int j = tid >> 1, fh = (tid & 1) * 16;
    const float* src = g_qk + ((size_t)bh*640 + s_kt[j])*32 + fh;
    float buf[16]; float ss = 0.f;
    #pragma unroll
    for (int u=0;u<16;u+=4){
      float4 a = *(const float4*)(src+u);
      buf[u]=a.x; buf[u+1]=a.y; buf[u+2]=a.z; buf[u+3]=a.w;
      ss += a.x*a.x + a.y*a.y + a.z*a.z + a.w*a.w;
    }
    ss += __shfl_xor_sync(0xffffffffu, ss, 1);
    float inv = 1.f / fmaxf(sqrtf(ss), 1e-6f);
    #pragma unroll
    for (int u=0;u<16;u++) s_kT[(fh+u)*KT_PAD + j] = buf[u]*inv;
  }
  // Load V row-major
  {
    int j = tid >> 1, fh = (tid & 1) * 16;
    const float* src = g_v + ((size_t)bh*640 + s_kt[j])*32 + fh;
    float* dst = s_v + j*32 + fh;
    #pragma unroll
    for (int u=0;u<16;u+=4) *(float4*)(dst+u) = *(const float4*)(src+u);
  }
  __syncthreads();

  // ---- dots microkernel: 64x128x32, thread tile 4x8 (ty=i-tile, tx=j-tile) ----
  int ty = tid >> 4, tx = tid & 15;   // i0 = ty*4, j0 = tx*8
  float acc[4][8];
  #pragma unroll
  for (int a=0;a<4;a++)
    #pragma unroll
    for (int b=0;b<8;b++) acc[a][b]=0.f;

  #pragma unroll 8
  for (int k=0;k<32;k++){
    float4 q  = *(float4*)&s_qT[k*QT_PAD + ty*4];
    float4 b0 = *(float4*)&s_kT[k*KT_PAD + tx*8];
    float4 b1 = *(float4*)&s_kT[k*KT_PAD + tx*8 + 4];
    float qa[4] = {q.x,q.y,q.z,q.w};
    float kb[8] = {b0.x,b0.y,b0.z,b0.w,b1.x,b1.y,b1.z,b1.w};
    #pragma unroll
    for (int a=0;a<4;a++)
      #pragma unroll
      for (int b=0;b<8;b++) acc[a][b] += qa[a]*kb[b];
  }

  // scale + self-mask
  int qtok[4], ktok[8];
  #pragma unroll
  for (int a=0;a<4;a++) qtok[a] = s_qt[ty*4+a];
  #pragma unroll
  for (int b=0;b<8;b++) ktok[b] = s_kt[tx*8+b];
  #pragma unroll
  for (int a=0;a<4;a++)
    #pragma unroll
    for (int b=0;b<8;b++){
      float d = acc[a][b]*0.17677669529663687f;
      acc[a][b] = (ktok[b]==qtok[a]) ? -50000.f : d;
    }

  // row softmax over 128 cols: reduce over tx group (16 lanes, same half-warp)
  float lse[4];
  #pragma unroll
  for (int a=0;a<4;a++){
    float m = acc[a][0];
    #pragma unroll
    for (int b=1;b<8;b++) m = fmaxf(m, acc[a][b]);
    #pragma unroll
    for (int o=8;o>0;o>>=1) m = fmaxf(m, __shfl_xor_sync(0xffffffffu, m, o, 16));
    float s = 0.f;
    #pragma unroll
    for (int b=0;b<8;b++) s += __expf(acc[a][b]-m);
    #pragma unroll
    for (int o=8;o>0;o>>=1) s += __shfl_xor_sync(0xffffffffu, s, o, 16);
    lse[a] = m + __logf(s);
  }
  if (tx == 0){
    #pragma unroll
    for (int a=0;a<4;a++)
      g_logit[(bh*NHASH+h)*T + qtok[a]] = lse[a];
  }

  __syncthreads();   // dots reads of s_qT/s_kT done before s_p overwrite

  #pragma unroll
  for (int a=0;a<4;a++){
    float4 p0, p1;
    p0.x=__expf(acc[a][0]-lse[a]); p0.y=__expf(acc[a][1]-lse[a]);
    p0.z=__expf(acc[a][2]-lse[a]); p0.w=__expf(acc[a][3]-lse[a]);
    p1.x=__expf(acc[a][4]-lse[a]); p1.y=__expf(acc[a][5]-lse[a]);
    p1.z=__expf(acc[a][6]-lse[a]); p1.w=__expf(acc[a][7]-lse[a]);
    *(float4*)&s_p[(ty*4+a)*P_PAD + tx*8]     = p0;
    *(float4*)&s_p[(ty*4+a)*P_PAD + tx*8 + 4] = p1;
  }
  __syncthreads();

  // ---- PV: 64x32x128, 128 threads, thread tile rows {iy, iy+32} x 8 dims ----
  if (tid < 128){
    int iy = tid >> 2;          // 0..31
    int d0 = (tid & 3) * 8;
    float o0[8], o1[8];
    #pragma unroll
    for (int d=0;d<8;d++){ o0[d]=0.f; o1[d]=0.f; }
    const float* p0r = s_p + iy*P_PAD;
    const float* p1r = s_p + (iy+32)*P_PAD;
    #pragma unroll 4
    for (int j=0;j<128;j++){
      float p0 = p0r[j];
      float p1 = p1r[j];
      float4 v0 = *(float4*)&s_v[j*32 + d0];
      float4 v1 = *(float4*)&s_v[j*32 + d0 + 4];
      float vv[8] = {v0.x,v0.y,v0.z,v0.w,v1.x,v1.y,v1.z,v1.w};
      #pragma unroll
      for (int d=0;d<8;d++){ o0[d] += p0*vv[d]; o1[d] += p1*vv[d]; }
    }
    size_t base = (size_t)(bh*NHASH+h)*T;
    float* dst0 = g_ohash + (base + s_qt[iy])*32 + d0;
    float* dst1 = g_ohash + (base + s_qt[iy+32])*32 + d0;
    *(float4*)dst0     = make_float4(o0[0],o0[1],o0[2],o0[3]);
    *(float4*)(dst0+4) = make_float4(o0[4],o0[5],o0[6],o0[7]);
    *(float4*)dst1     = make_float4(o1[0],o1[1],o1[2],o1[3]);
    *(float4*)(dst1+4) = make_float4(o1[4],o1[5],o1[6],o1[7]);
  }
}

// ---------------- stage 5: combine hashes, merge heads (float4) ----------------
__global__ void combine_kernel(){
  int idx = blockIdx.x*blockDim.x + threadIdx.x;
  if (idx >= BHDIM*T*8) return;
  int dq  = idx & 7;               // float4 group
  int pos = (idx >> 3) % 640;
  int bh  = idx / (640*8);
  float l[NHASH];
  #pragma unroll
  for (int h=0;h<NHASH;h++) l[h] = g_logit[(bh*NHASH+h)*T + pos];
  float m = l[0];
  #pragma unroll
  for (int h=1;h<NHASH;h++) m = fmaxf(m, l[h]);
  float s = 0.f;
  float e[NHASH];
  #pragma unroll
  for (int h=0;h<NHASH;h++){ e[h] = __expf(l[h]-m); s += e[h]; }
  float inv = 1.f/s;
  float4 acc = make_float4(0.f,0.f,0.f,0.f);
  #pragma unroll
  for (int h=0;h<NHASH;h++){
    float w = e[h]*inv;
    float4 v = *(const float4*)(g_ohash + ((size_t)(bh*NHASH+h)*T + pos)*32 + dq*4);
    acc.x += w*v.x; acc.y += w*v.y; acc.z += w*v.z; acc.w += w*v.w;
  }
  int b = bh>>3, head = bh&7;
  *(float4*)(g_omerged + ((size_t)b*640 + pos)*256 + head*32 + dq*4) = acc;
}

// ---------------- stage 6: output GEMM + bias ----------------
__global__ __launch_bounds__(256) void gemm_out_kernel(const float* __restrict__ W,
                                                       const float* __restrict__ bias,
                                                       float* __restrict__ out){
  __shared__ float As[32][64];
  __shared__ float Bs[32][64];
  int tid = threadIdx.x;
  int m0 = blockIdx.y*64, n0 = blockIdx.x*64;
  int ty = tid>>4, tx = tid&15;
  float acc[4][4];
  #pragma unroll
  for (int i=0;i<4;i++)
    #pragma unroll
    for (int j=0;j<4;j++) acc[i][j]=0.f;

  for (int k0=0;k0<256;k0+=32){
    int am = tid>>2, akq = tid&3;
    const float* asrc = g_omerged + (size_t)(m0+am)*256 + k0 + akq*8;
    float4 a0 = *(const float4*)asrc;
    float4 a1 = *(const float4*)(asrc+4);
    As[akq*8+0][am]=a0.x; As[akq*8+1][am]=a0.y; As[akq*8+2][am]=a0.z; As[akq*8+3][am]=a0.w;
    As[akq*8+4][am]=a1.x; As[akq*8+5][am]=a1.y; As[akq*8+6][am]=a1.z; As[akq*8+7][am]=a1.w;

    int bk = tid>>3, bnq = tid&7;
    const float* bsrc = W + (size_t)(k0+bk)*256 + n0 + bnq*8;
    *(float4*)&Bs[bk][bnq*8]   = *(const float4*)bsrc;
    *(float4*)&Bs[bk][bnq*8+4] = *(const float4*)(bsrc+4);
    __syncthreads();

    #pragma unroll
    for (int k=0;k<32;k++){
      float4 av = *(float4*)&As[k][ty*4];
      float4 bv = *(float4*)&Bs[k][tx*4];
      float aa[4] = {av.x,av.y,av.z,av.w};
      float bb[4] = {bv.x,bv.y,bv.z,bv.w};
      #pragma unroll
      for (int i2=0;i2<4;i2++)
        #pragma unroll
        for (int j2=0;j2<4;j2++) acc[i2][j2] += aa[i2]*bb[j2];
    }
    __syncthreads();
  }
  #pragma unroll
  for (int i2=0;i2<4;i2++){
    int row = m0 + ty*4 + i2;
    #pragma unroll
    for (int j2=0;j2<4;j2++){
      int col = n0 + tx*4 + j2;
      out[(size_t)row*256 + col] = acc[i2][j2] + bias[col];
    }
  }
}

// ---------------- launch ----------------
extern "C" void kernel_launch(void* const* d_in, const int* in_sizes, int n_in,
                              void* d_out, int out_size){
  const float* x     = (const float*)d_in[0];
  const float* w_qk  = (const float*)d_in[1];
  const float* w_v   = (const float*)d_in[2];
  const float* w_out = (const float*)d_in[3];
  const float* b_out = (const float*)d_in[4];
  const float* rot   = (const float*)d_in[5];
  float* out = (float*)d_out;

  frontend_kernel<<<(BATCH*640*256+255)/256, 256>>>(x);
  gemm_qkv_kernel<<<dim3(4,160), 256>>>(w_qk, w_v);
  bucket_kernel<<<(BHDIM*NHASH*T+255)/256, 256>>>(rot);
  sort_kernel<<<BHDIM*NHASH, 320>>>();
  cudaFuncSetAttribute(attn_kernel, cudaFuncAttributeMaxDynamicSharedMemorySize, SMEM_ATTN);
  attn_kernel<<<BHDIM*NCHUNK, 256, SMEM_ATTN>>>();
  combine_kernel<<<(BHDIM*T*8+255)/256, 256>>>();
  gemm_out_kernel<<<dim3(4,160), 256>>>(w_out, b_out, out);
}